// round 1
// baseline (speedup 1.0000x reference)
#include <cuda_runtime.h>

// AccuracyMetricLoss: per-day (96-elem) RMS relative-error score, mean over days.
// score_d = (1 - sqrt(mean_j ((t-p)/max(t,thresh))^2)) * 100 ; out = mean_d score_d
//
// Strategy: warp-per-day (96 floats = 3 aligned 128B lines per array -> fully
// coalesced, lane reads base+lane, +32, +64). Per-block partial sums written to
// fixed slots in a __device__ array (deterministic, no atomics, no zeroing
// needed across graph replays). Tiny finalize kernel reduces partials in double.

#define T_LEN 96
#define NBLOCKS 592          // 4 * 148 SMs
#define NTHREADS 256         // 8 warps/block
#define WARPS_PER_BLOCK (NTHREADS / 32)
#define TOTAL_WARPS (NBLOCKS * WARPS_PER_BLOCK)

__device__ float g_partials[NBLOCKS];

__global__ __launch_bounds__(NTHREADS) void score_kernel(
    const float* __restrict__ pred,
    const float* __restrict__ tru,
    int num_days)
{
    // Match reference float32 constants: cap = f32(1602.1333...), thresh = 0.2f * cap
    const float cap    = 1602.1333333333334f;
    const float thresh = 0.2f * cap;
    const float inv_T  = 1.0f / 96.0f;

    const int lane = threadIdx.x & 31;
    const int warp = (blockIdx.x * WARPS_PER_BLOCK) + (threadIdx.x >> 5);

    float acc = 0.0f;  // per-warp score accumulator (identical across lanes post-reduce)

    for (int day = warp; day < num_days; day += TOTAL_WARPS) {
        const long base = (long)day * T_LEN + lane;

        // 6 independent streaming loads (evict-first: no reuse, dataset >> L2)
        float t0 = __ldcs(tru  + base);
        float t1 = __ldcs(tru  + base + 32);
        float t2 = __ldcs(tru  + base + 64);
        float p0 = __ldcs(pred + base);
        float p1 = __ldcs(pred + base + 32);
        float p2 = __ldcs(pred + base + 64);

        float d0 = (t0 > thresh) ? t0 : thresh;
        float d1 = (t1 > thresh) ? t1 : thresh;
        float d2 = (t2 > thresh) ? t2 : thresh;

        float r0 = __fdividef(t0 - p0, d0);
        float r1 = __fdividef(t1 - p1, d1);
        float r2 = __fdividef(t2 - p2, d2);

        float r = r0 * r0 + r1 * r1 + r2 * r2;

        // warp sum over 96 elements (3 per lane)
        #pragma unroll
        for (int o = 16; o > 0; o >>= 1)
            r += __shfl_xor_sync(0xffffffffu, r, o);

        acc += (1.0f - sqrtf(r * inv_T)) * 100.0f;
    }

    // block reduce: lane 0 of each warp -> smem -> warp 0
    __shared__ float warp_acc[WARPS_PER_BLOCK];
    if (lane == 0) warp_acc[threadIdx.x >> 5] = acc;
    __syncthreads();

    if (threadIdx.x < 32) {
        float v = (threadIdx.x < WARPS_PER_BLOCK) ? warp_acc[threadIdx.x] : 0.0f;
        #pragma unroll
        for (int o = 16; o > 0; o >>= 1)
            v += __shfl_xor_sync(0xffffffffu, v, o);
        if (threadIdx.x == 0) g_partials[blockIdx.x] = v;
    }
}

__global__ void finalize_kernel(float* __restrict__ out, int num_days)
{
    // single warp: reduce NBLOCKS partials in double, divide, store
    double a = 0.0;
    for (int i = threadIdx.x; i < NBLOCKS; i += 32)
        a += (double)g_partials[i];
    #pragma unroll
    for (int o = 16; o > 0; o >>= 1)
        a += __shfl_xor_sync(0xffffffffu, a, o);
    if (threadIdx.x == 0)
        out[0] = (float)(a / (double)num_days);
}

extern "C" void kernel_launch(void* const* d_in, const int* in_sizes, int n_in,
                              void* d_out, int out_size)
{
    const float* pred = (const float*)d_in[0];
    const float* tru  = (const float*)d_in[1];
    float* out = (float*)d_out;

    int num_days = in_sizes[0] / T_LEN;

    score_kernel<<<NBLOCKS, NTHREADS>>>(pred, tru, num_days);
    finalize_kernel<<<1, 32>>>(out, num_days);
}

// round 3
// speedup vs baseline: 1.3677x; 1.3677x over previous
#include <cuda_runtime.h>

// AccuracyMetricLoss: per-day (96-elem) RMS relative-error score, mean over days.
// score_d = (1 - sqrt(mean_j ((t-p)/max(t,thresh))^2)) * 100 ; out = mean_d score_d
//
// R3: single fused kernel.
//  - warp processes 4 consecutive days per trip: 24 independent streaming LDGs
//    batched up front (high MLP), then 4 INDEPENDENT 5-step shuffle trees
//    (they pipeline; redux.f32 does not exist on sm_103a).
//  - last-block-finalizes pattern removes the second kernel launch (~11us).
//    Counter is reset by the last block => graph-replayable, deterministic.

#define T_LEN 96
#define NBLOCKS 592          // 4 * 148 SMs
#define NTHREADS 256         // 8 warps/block
#define WARPS_PER_BLOCK (NTHREADS / 32)
#define TOTAL_WARPS (NBLOCKS * WARPS_PER_BLOCK)
#define DAYS_PER_TRIP 4

__device__ float g_partials[NBLOCKS];
__device__ unsigned int g_counter = 0;

__global__ __launch_bounds__(NTHREADS) void score_kernel(
    const float* __restrict__ pred,
    const float* __restrict__ tru,
    float* __restrict__ out,
    int num_days)
{
    const float cap    = 1602.1333333333334f;
    const float thresh = 0.2f * cap;
    const float inv_T  = 1.0f / 96.0f;

    const int lane = threadIdx.x & 31;
    const int warp = (blockIdx.x * WARPS_PER_BLOCK) + (threadIdx.x >> 5);

    float acc = 0.0f;

    for (int day0 = warp * DAYS_PER_TRIP; day0 < num_days;
         day0 += TOTAL_WARPS * DAYS_PER_TRIP) {

        const int nd = min(DAYS_PER_TRIP, num_days - day0);

        if (nd == DAYS_PER_TRIP) {
            // fast path: 24 independent loads batched up front
            float t[4][3], p[4][3];
            const long base = (long)day0 * T_LEN + lane;
            #pragma unroll
            for (int d = 0; d < 4; d++) {
                #pragma unroll
                for (int j = 0; j < 3; j++) {
                    t[d][j] = __ldcs(tru  + base + d * T_LEN + j * 32);
                    p[d][j] = __ldcs(pred + base + d * T_LEN + j * 32);
                }
            }
            // 4 independent per-day partial sums
            float r[4];
            #pragma unroll
            for (int d = 0; d < 4; d++) {
                r[d] = 0.0f;
                #pragma unroll
                for (int j = 0; j < 3; j++) {
                    float tv = t[d][j];
                    float dv = (tv > thresh) ? tv : thresh;
                    float e  = __fdividef(tv - p[d][j], dv);
                    r[d] += e * e;
                }
            }
            // 4 independent shuffle trees -> pipelined in issue
            #pragma unroll
            for (int o = 16; o > 0; o >>= 1) {
                #pragma unroll
                for (int d = 0; d < 4; d++)
                    r[d] += __shfl_xor_sync(0xffffffffu, r[d], o);
            }
            #pragma unroll
            for (int d = 0; d < 4; d++)
                acc += (1.0f - sqrtf(r[d] * inv_T)) * 100.0f;
        } else {
            for (int d = 0; d < nd; d++) {
                const long base = (long)(day0 + d) * T_LEN + lane;
                float r = 0.0f;
                #pragma unroll
                for (int j = 0; j < 3; j++) {
                    float tv = __ldcs(tru  + base + j * 32);
                    float pv = __ldcs(pred + base + j * 32);
                    float dv = (tv > thresh) ? tv : thresh;
                    float e  = __fdividef(tv - pv, dv);
                    r += e * e;
                }
                #pragma unroll
                for (int o = 16; o > 0; o >>= 1)
                    r += __shfl_xor_sync(0xffffffffu, r, o);
                acc += (1.0f - sqrtf(r * inv_T)) * 100.0f;
            }
        }
    }

    // block reduce into g_partials[blockIdx.x]
    __shared__ float warp_acc[WARPS_PER_BLOCK];
    if (lane == 0) warp_acc[threadIdx.x >> 5] = acc;
    __syncthreads();

    __shared__ bool is_last;
    if (threadIdx.x == 0) {
        float v = 0.0f;
        #pragma unroll
        for (int w = 0; w < WARPS_PER_BLOCK; w++) v += warp_acc[w];
        g_partials[blockIdx.x] = v;
        __threadfence();
        unsigned int prev = atomicAdd(&g_counter, 1u);
        is_last = (prev == (unsigned int)(gridDim.x - 1));
    }
    __syncthreads();

    // last block finalizes: fixed-order double reduction over NBLOCKS partials
    if (is_last) {
        double a = 0.0;
        for (int i = threadIdx.x; i < NBLOCKS; i += NTHREADS)
            a += (double)g_partials[i];

        __shared__ double dacc[WARPS_PER_BLOCK];
        #pragma unroll
        for (int o = 16; o > 0; o >>= 1)
            a += __shfl_xor_sync(0xffffffffu, a, o);
        if (lane == 0) dacc[threadIdx.x >> 5] = a;
        __syncthreads();
        if (threadIdx.x == 0) {
            double s = 0.0;
            #pragma unroll
            for (int w = 0; w < WARPS_PER_BLOCK; w++) s += dacc[w];
            out[0] = (float)(s / (double)num_days);
            g_counter = 0;           // reset for next graph replay
            __threadfence();
        }
    }
}

extern "C" void kernel_launch(void* const* d_in, const int* in_sizes, int n_in,
                              void* d_out, int out_size)
{
    const float* pred = (const float*)d_in[0];
    const float* tru  = (const float*)d_in[1];
    float* out = (float*)d_out;

    int num_days = in_sizes[0] / T_LEN;

    score_kernel<<<NBLOCKS, NTHREADS>>>(pred, tru, out, num_days);
}

// round 4
// speedup vs baseline: 1.4545x; 1.0635x over previous
#include <cuda_runtime.h>

// AccuracyMetricLoss: per-day (96-elem) RMS relative-error score, mean over days.
// score_d = (1 - sqrt(mean_j ((t-p)/max(t,thresh))^2)) * 100 ; out = mean_d score_d
//
// R4: 8-lanes-per-day segmented layout with float4 loads.
//  - warp handles 4 consecutive days/trip: lane l (group g=l>>3, k=l&7) loads
//    float4 #(g*24 + k + 8i), i=0..2 -> each LDG.128 covers 4 full 128B lines,
//    perfectly coalesced. 6 LDG.128/trip (was 24 LDG.32).
//  - day reduction = 3 xor-shuffles within 8-lane groups (was 5 full-warp).
//  - each day's score lands in 8 lanes' acc -> finalize divides by 8*num_days.
//  - 1184 blocks => 64 warps/SM (full occupancy), launch_bounds caps regs at 32.
//  - last-block-finalizes (deterministic fixed-order double sum, counter reset).

#define T_LEN 96
#define F4_PER_DAY 24
#define NBLOCKS 1184         // 8 * 148 SMs
#define NTHREADS 256         // 8 warps/block
#define WARPS_PER_BLOCK (NTHREADS / 32)
#define TOTAL_WARPS (NBLOCKS * WARPS_PER_BLOCK)
#define DAYS_PER_TRIP 4

__device__ float g_partials[NBLOCKS];
__device__ unsigned int g_counter = 0;

__device__ __forceinline__ float day_err_sq(float4 t, float4 p,
                                            float thresh)
{
    float d0 = (t.x > thresh) ? t.x : thresh;
    float d1 = (t.y > thresh) ? t.y : thresh;
    float d2 = (t.z > thresh) ? t.z : thresh;
    float d3 = (t.w > thresh) ? t.w : thresh;
    float e0 = __fdividef(t.x - p.x, d0);
    float e1 = __fdividef(t.y - p.y, d1);
    float e2 = __fdividef(t.z - p.z, d2);
    float e3 = __fdividef(t.w - p.w, d3);
    return e0 * e0 + e1 * e1 + e2 * e2 + e3 * e3;
}

__global__ __launch_bounds__(NTHREADS, 8) void score_kernel(
    const float* __restrict__ pred,
    const float* __restrict__ tru,
    float* __restrict__ out,
    int num_days)
{
    const float cap    = 1602.1333333333334f;
    const float thresh = 0.2f * cap;
    const float inv_T  = 1.0f / 96.0f;

    const int lane = threadIdx.x & 31;
    const int g    = lane >> 3;          // day group within warp (0..3)
    const int k    = lane & 7;           // lane within group
    const int warp = (blockIdx.x * WARPS_PER_BLOCK) + (threadIdx.x >> 5);

    const float4* __restrict__ tru4  = (const float4*)tru;
    const float4* __restrict__ pred4 = (const float4*)pred;

    float acc = 0.0f;

    for (int day0 = warp * DAYS_PER_TRIP; day0 < num_days;
         day0 += TOTAL_WARPS * DAYS_PER_TRIP) {

        if (day0 + DAYS_PER_TRIP <= num_days) {
            // fast path: 6 fully-coalesced LDG.128 per warp
            const long b = (long)day0 * F4_PER_DAY + g * F4_PER_DAY + k;
            float4 t0 = __ldcs(tru4  + b);
            float4 t1 = __ldcs(tru4  + b + 8);
            float4 t2 = __ldcs(tru4  + b + 16);
            float4 p0 = __ldcs(pred4 + b);
            float4 p1 = __ldcs(pred4 + b + 8);
            float4 p2 = __ldcs(pred4 + b + 16);

            float r = day_err_sq(t0, p0, thresh)
                    + day_err_sq(t1, p1, thresh)
                    + day_err_sq(t2, p2, thresh);

            // reduce within 8-lane group (stays inside group: xor of low 3 bits)
            r += __shfl_xor_sync(0xffffffffu, r, 4);
            r += __shfl_xor_sync(0xffffffffu, r, 2);
            r += __shfl_xor_sync(0xffffffffu, r, 1);

            acc += (1.0f - sqrtf(r * inv_T)) * 100.0f;   // counted 8x per day
        } else {
            // tail: full-warp per day, scalar loads; add on lanes 0..7 only
            // so each day is still counted exactly 8x.
            for (int d = 0; d < num_days - day0; d++) {
                const long base = (long)(day0 + d) * T_LEN + lane;
                float r = 0.0f;
                #pragma unroll
                for (int j = 0; j < 3; j++) {
                    float tv = __ldcs(tru  + base + j * 32);
                    float pv = __ldcs(pred + base + j * 32);
                    float dv = (tv > thresh) ? tv : thresh;
                    float e  = __fdividef(tv - pv, dv);
                    r += e * e;
                }
                #pragma unroll
                for (int o = 16; o > 0; o >>= 1)
                    r += __shfl_xor_sync(0xffffffffu, r, o);
                if (lane < 8)
                    acc += (1.0f - sqrtf(r * inv_T)) * 100.0f;
            }
        }
    }

    // block reduce into g_partials[blockIdx.x]
    #pragma unroll
    for (int o = 16; o > 0; o >>= 1)
        acc += __shfl_xor_sync(0xffffffffu, acc, o);

    __shared__ float warp_acc[WARPS_PER_BLOCK];
    if (lane == 0) warp_acc[threadIdx.x >> 5] = acc;
    __syncthreads();

    __shared__ bool is_last;
    if (threadIdx.x == 0) {
        float v = 0.0f;
        #pragma unroll
        for (int w = 0; w < WARPS_PER_BLOCK; w++) v += warp_acc[w];
        g_partials[blockIdx.x] = v;
        __threadfence();
        unsigned int prev = atomicAdd(&g_counter, 1u);
        is_last = (prev == (unsigned int)(gridDim.x - 1));
    }
    __syncthreads();

    // last block finalizes: fixed-order double reduction over NBLOCKS partials
    if (is_last) {
        double a = 0.0;
        for (int i = threadIdx.x; i < NBLOCKS; i += NTHREADS)
            a += (double)g_partials[i];

        __shared__ double dacc[WARPS_PER_BLOCK];
        #pragma unroll
        for (int o = 16; o > 0; o >>= 1)
            a += __shfl_xor_sync(0xffffffffu, a, o);
        if (lane == 0) dacc[threadIdx.x >> 5] = a;
        __syncthreads();
        if (threadIdx.x == 0) {
            double s = 0.0;
            #pragma unroll
            for (int w = 0; w < WARPS_PER_BLOCK; w++) s += dacc[w];
            out[0] = (float)(s / (8.0 * (double)num_days));
            g_counter = 0;           // reset for next graph replay
            __threadfence();
        }
    }
}

extern "C" void kernel_launch(void* const* d_in, const int* in_sizes, int n_in,
                              void* d_out, int out_size)
{
    const float* pred = (const float*)d_in[0];
    const float* tru  = (const float*)d_in[1];
    float* out = (float*)d_out;

    int num_days = in_sizes[0] / T_LEN;

    score_kernel<<<NBLOCKS, NTHREADS>>>(pred, tru, out, num_days);
}

// round 5
// speedup vs baseline: 1.4574x; 1.0021x over previous
#include <cuda_runtime.h>

// AccuracyMetricLoss: per-day (96-elem) RMS relative-error score, mean over days.
// score_d = (1 - sqrt(mean_j ((t-p)/max(t,thresh))^2)) * 100 ; out = mean_d score_d
//
// R5:
//  - 8-lanes-per-day float4 layout (6 LDG.128/trip, fully coalesced).
//  - __launch_bounds__(256, 4) -> 64-reg budget so ptxas can keep all 6 float4
//    pairs live and batch the loads (R4's 32-reg cap serialized them, MLP~2).
//    592 blocks = 4 CTAs/SM = 32 warps/SM: ~98KB in flight/SM >> ~30KB needed.
//  - per-warp CONTIGUOUS day ranges (w*D/W..(w+1)*D/W): removes the 14%
//    trip-quantization imbalance of the strided schedule; tail <=3 days uses
//    partial groups on the same float4 path.
//  - last-block-finalizes (deterministic fixed-order double sum, counter reset).

#define T_LEN 96
#define F4_PER_DAY 24
#define NBLOCKS 592          // 4 * 148 SMs
#define NTHREADS 256         // 8 warps/block
#define WARPS_PER_BLOCK (NTHREADS / 32)
#define TOTAL_WARPS (NBLOCKS * WARPS_PER_BLOCK)

__device__ float g_partials[NBLOCKS];
__device__ unsigned int g_counter = 0;

__device__ __forceinline__ float day_err_sq(float4 t, float4 p, float thresh)
{
    float d0 = (t.x > thresh) ? t.x : thresh;
    float d1 = (t.y > thresh) ? t.y : thresh;
    float d2 = (t.z > thresh) ? t.z : thresh;
    float d3 = (t.w > thresh) ? t.w : thresh;
    float e0 = __fdividef(t.x - p.x, d0);
    float e1 = __fdividef(t.y - p.y, d1);
    float e2 = __fdividef(t.z - p.z, d2);
    float e3 = __fdividef(t.w - p.w, d3);
    return e0 * e0 + e1 * e1 + e2 * e2 + e3 * e3;
}

__global__ __launch_bounds__(NTHREADS, 4) void score_kernel(
    const float* __restrict__ pred,
    const float* __restrict__ tru,
    float* __restrict__ out,
    int num_days)
{
    const float cap    = 1602.1333333333334f;
    const float thresh = 0.2f * cap;
    const float inv_T  = 1.0f / 96.0f;

    const int lane = threadIdx.x & 31;
    const int g    = lane >> 3;          // day group within warp (0..3)
    const int k    = lane & 7;           // lane within group
    const int warp = (blockIdx.x * WARPS_PER_BLOCK) + (threadIdx.x >> 5);

    const float4* __restrict__ tru4  = (const float4*)tru;
    const float4* __restrict__ pred4 = (const float4*)pred;

    // contiguous per-warp day range: near-perfect balance (<=1 day skew)
    int day_s = (int)(((long)warp       * num_days) / TOTAL_WARPS);
    int day_e = (int)(((long)(warp + 1) * num_days) / TOTAL_WARPS);

    float acc = 0.0f;

    int day = day_s;
    for (; day + 4 <= day_e; day += 4) {
        // 6 fully-coalesced LDG.128 per warp, batched (64-reg budget)
        const long b = (long)(day + g) * F4_PER_DAY + k;
        float4 t0 = __ldcs(tru4  + b);
        float4 t1 = __ldcs(tru4  + b + 8);
        float4 t2 = __ldcs(tru4  + b + 16);
        float4 p0 = __ldcs(pred4 + b);
        float4 p1 = __ldcs(pred4 + b + 8);
        float4 p2 = __ldcs(pred4 + b + 16);

        float r = day_err_sq(t0, p0, thresh)
                + day_err_sq(t1, p1, thresh)
                + day_err_sq(t2, p2, thresh);

        // reduce within 8-lane group (xor of low 3 bits stays in-group)
        r += __shfl_xor_sync(0xffffffffu, r, 4);
        r += __shfl_xor_sync(0xffffffffu, r, 2);
        r += __shfl_xor_sync(0xffffffffu, r, 1);

        acc += (1.0f - sqrtf(r * inv_T)) * 100.0f;   // counted 8x per day
    }

    // tail: 0..3 days, groups g < nd active, same float4 path
    {
        const int nd = day_e - day;
        if (nd > 0) {
            float r = 0.0f;
            if (g < nd) {
                const long b = (long)(day + g) * F4_PER_DAY + k;
                float4 t0 = __ldcs(tru4  + b);
                float4 t1 = __ldcs(tru4  + b + 8);
                float4 t2 = __ldcs(tru4  + b + 16);
                float4 p0 = __ldcs(pred4 + b);
                float4 p1 = __ldcs(pred4 + b + 8);
                float4 p2 = __ldcs(pred4 + b + 16);
                r = day_err_sq(t0, p0, thresh)
                  + day_err_sq(t1, p1, thresh)
                  + day_err_sq(t2, p2, thresh);
            }
            r += __shfl_xor_sync(0xffffffffu, r, 4);
            r += __shfl_xor_sync(0xffffffffu, r, 2);
            r += __shfl_xor_sync(0xffffffffu, r, 1);
            if (g < nd)
                acc += (1.0f - sqrtf(r * inv_T)) * 100.0f;
        }
    }

    // warp sum, then block reduce into g_partials[blockIdx.x]
    #pragma unroll
    for (int o = 16; o > 0; o >>= 1)
        acc += __shfl_xor_sync(0xffffffffu, acc, o);

    __shared__ float warp_acc[WARPS_PER_BLOCK];
    if (lane == 0) warp_acc[threadIdx.x >> 5] = acc;
    __syncthreads();

    __shared__ bool is_last;
    if (threadIdx.x == 0) {
        float v = 0.0f;
        #pragma unroll
        for (int w = 0; w < WARPS_PER_BLOCK; w++) v += warp_acc[w];
        g_partials[blockIdx.x] = v;
        __threadfence();
        unsigned int prev = atomicAdd(&g_counter, 1u);
        is_last = (prev == (unsigned int)(gridDim.x - 1));
    }
    __syncthreads();

    // last block finalizes: fixed-order double reduction over NBLOCKS partials
    if (is_last) {
        double a = 0.0;
        for (int i = threadIdx.x; i < NBLOCKS; i += NTHREADS)
            a += (double)g_partials[i];

        __shared__ double dacc[WARPS_PER_BLOCK];
        #pragma unroll
        for (int o = 16; o > 0; o >>= 1)
            a += __shfl_xor_sync(0xffffffffu, a, o);
        if (lane == 0) dacc[threadIdx.x >> 5] = a;
        __syncthreads();
        if (threadIdx.x == 0) {
            double s = 0.0;
            #pragma unroll
            for (int w = 0; w < WARPS_PER_BLOCK; w++) s += dacc[w];
            out[0] = (float)(s / (8.0 * (double)num_days));
            g_counter = 0;           // reset for next graph replay
            __threadfence();
        }
    }
}

extern "C" void kernel_launch(void* const* d_in, const int* in_sizes, int n_in,
                              void* d_out, int out_size)
{
    const float* pred = (const float*)d_in[0];
    const float* tru  = (const float*)d_in[1];
    float* out = (float*)d_out;

    int num_days = in_sizes[0] / T_LEN;

    score_kernel<<<NBLOCKS, NTHREADS>>>(pred, tru, out, num_days);
}